// round 6
// baseline (speedup 1.0000x reference)
#include <cuda_runtime.h>
#include <cuda_fp16.h>
#include <cstdint>
#include <cstddef>

// Problem sizes (fixed)
#define BATCH 4096
#define HDIM  1024
#define KDIM  1024
#define NDIM  4096

// ---------------------------------------------------------------------------
// Scratch (device globals -- allocation is forbidden)
// ---------------------------------------------------------------------------
__device__ __align__(1024) __half g_xh [BATCH * KDIM];
__device__ __align__(1024) __half g_hh [BATCH * KDIM];
__device__ __align__(1024) __half g_wih[NDIM  * KDIM];
__device__ __align__(1024) __half g_whh[NDIM  * KDIM];
__device__ __align__(16) __half g_pre_ih[(size_t)BATCH * NDIM];   // fp16 pre-activations
__device__ __align__(16) __half g_pre_hh[(size_t)BATCH * NDIM];

// ---------------------------------------------------------------------------
// fp32 -> fp16 preconversion.  Each thread: 8 floats -> 8 halves (16B store).
// ---------------------------------------------------------------------------
__global__ void __launch_bounds__(256) cvt_kernel(
    const float4* __restrict__ x, const float4* __restrict__ h,
    const float4* __restrict__ wih, const float4* __restrict__ whh)
{
    int i = blockIdx.x * blockDim.x + threadIdx.x;
    const float4* src; __half* dst;
    switch (blockIdx.y) {
        case 0:  src = x;   dst = g_xh;  break;
        case 1:  src = h;   dst = g_hh;  break;
        case 2:  src = wih; dst = g_wih; break;
        default: src = whh; dst = g_whh; break;
    }
    float4 v0 = src[2 * i];
    float4 v1 = src[2 * i + 1];
    __half2 o[4];
    o[0] = __floats2half2_rn(v0.x, v0.y);
    o[1] = __floats2half2_rn(v0.z, v0.w);
    o[2] = __floats2half2_rn(v1.x, v1.y);
    o[3] = __floats2half2_rn(v1.z, v1.w);
    *(uint4*)(dst + 8 * (size_t)i) = *(uint4*)o;
}

// ---------------------------------------------------------------------------
// fp16 GEMM: C[M,N] = A[M,K] @ W[N,K]^T, fp32 accumulate, fp16 output.
// CTA tile 128x128x64(halves), warp tile 64x32, 3-stage cp.async (single sync),
// ldmatrix (2-ks batches) + mma.m16n8k16.
// grid = (N/128, M/128, 2)  z: 0 = ih, 1 = hh.  block = 256 (8 warps, 2 CTA/SM)
// ---------------------------------------------------------------------------
#define BM 128
#define BN 128
#define BK 64                  // halves per k-tile (128 data bytes/row)
#define ROWB 144               // smem row stride (128 data + 16 pad, conflict-free)
#define STAGES 3
#define NK (KDIM / BK)         // 16
#define A_SM_BYTES (BM * ROWB)             // 18432
#define STAGE_BYTES (2 * A_SM_BYTES)       // 36864 (A then B)
#define SMEM_TOTAL (STAGES * STAGE_BYTES)  // 110592 (x2 CTA = 221184 <= 228KB)

__device__ __forceinline__ uint32_t smem_u32(const void* p) {
    uint32_t a;
    asm("{ .reg .u64 t; cvta.to.shared.u64 t, %1; cvt.u32.u64 %0, t; }" : "=r"(a) : "l"(p));
    return a;
}
__device__ __forceinline__ void cp16(uint32_t smem, const void* gmem) {
    asm volatile("cp.async.cg.shared.global [%0], [%1], 16;" :: "r"(smem), "l"(gmem));
}
#define LDSM_X4(r0, r1, r2, r3, addr) \
    asm volatile("ldmatrix.sync.aligned.m8n8.x4.shared.b16 {%0,%1,%2,%3}, [%4];" \
        : "=r"(r0), "=r"(r1), "=r"(r2), "=r"(r3) : "r"(addr))

__global__ void __launch_bounds__(256, 2) gemm_f16()
{
    extern __shared__ char smem[];
    const uint32_t sb = smem_u32(smem);
    const int tid  = threadIdx.x;
    const int lane = tid & 31;
    const int warp = tid >> 5;
    const int wm   = warp >> 2;   // 0..1 -> M 64-block
    const int wn   = warp & 3;    // 0..3 -> N 32-block

    const int z = blockIdx.z;
    const __half* __restrict__ A = z ? g_hh  : g_xh;
    const __half* __restrict__ W = z ? g_whh : g_wih;
    __half* __restrict__ C       = z ? g_pre_hh : g_pre_ih;
    const int bm = blockIdx.y * BM;
    const int bn = blockIdx.x * BN;

    float acc[4][4][4];
#pragma unroll
    for (int a = 0; a < 4; a++)
#pragma unroll
        for (int b = 0; b < 4; b++)
#pragma unroll
            for (int d = 0; d < 4; d++) acc[a][b][d] = 0.f;

    // loader: row = tid>>1 (0..127), 64B half = (tid&1); 4 cp16 each for A and B
    const int lrow  = tid >> 1;
    const int lhalf = tid & 1;
    const __half* gA0 = A + (size_t)(bm + lrow) * KDIM + lhalf * 32;
    const __half* gW0 = W + (size_t)(bn + lrow) * KDIM + lhalf * 32;
    const uint32_t sA0 = sb + lrow * ROWB + lhalf * 64;
    const uint32_t sB0 = sA0 + A_SM_BYTES;

    auto issue = [&](int kt, int buf) {
        const size_t ko = (size_t)kt * BK;
        const uint32_t so = buf * STAGE_BYTES;
        cp16(sA0 + so,      gA0 + ko);
        cp16(sA0 + so + 16, gA0 + ko + 8);
        cp16(sA0 + so + 32, gA0 + ko + 16);
        cp16(sA0 + so + 48, gA0 + ko + 24);
        cp16(sB0 + so,      gW0 + ko);
        cp16(sB0 + so + 16, gW0 + ko + 8);
        cp16(sB0 + so + 32, gW0 + ko + 16);
        cp16(sB0 + so + 48, gW0 + ko + 24);
        asm volatile("cp.async.commit_group;");
    };

    issue(0, 0); issue(1, 1);

    // fragment base addresses (per thread)
    const int l15 = lane & 15, lhi = lane >> 4;
    const uint32_t aBase = sb + (wm * 64 + l15) * ROWB + lhi * 16;
    const uint32_t bBase = sb + A_SM_BYTES + (wn * 32 + l15) * ROWB + lhi * 16;

    int cbuf = 0, pbuf = 2;
    for (int kt = 0; kt < NK; kt++) {
        if (kt < NK - 1) {
            asm volatile("cp.async.wait_group 1;");
        } else {
            asm volatile("cp.async.wait_group 0;");
        }
        __syncthreads();
        if (kt + 2 < NK) {                    // writes old consume buffer: safe
            issue(kt + 2, pbuf);
            pbuf = (pbuf == STAGES - 1) ? 0 : pbuf + 1;
        }

        const uint32_t so = cbuf * STAGE_BYTES;
        cbuf = (cbuf == STAGES - 1) ? 0 : cbuf + 1;

        // 4 k16 slices, processed as two 2-slice batches (keeps regs <= 128)
#pragma unroll
        for (int half = 0; half < 2; half++) {
            uint32_t a[2][4][4];
            uint32_t b[2][4][2];
#pragma unroll
            for (int q = 0; q < 2; q++) {
                const int ks = half * 2 + q;
#pragma unroll
                for (int mt = 0; mt < 4; mt++)
                    LDSM_X4(a[q][mt][0], a[q][mt][1], a[q][mt][2], a[q][mt][3],
                            aBase + so + mt * (16 * ROWB) + ks * 32);
                LDSM_X4(b[q][0][0], b[q][1][0], b[q][0][1], b[q][1][1],
                        bBase + so + ks * 32);
                LDSM_X4(b[q][2][0], b[q][3][0], b[q][2][1], b[q][3][1],
                        bBase + so + 16 * ROWB + ks * 32);
            }
#pragma unroll
            for (int q = 0; q < 2; q++)
#pragma unroll
                for (int mt = 0; mt < 4; mt++)
#pragma unroll
                    for (int nt = 0; nt < 4; nt++) {
                        asm volatile(
                            "mma.sync.aligned.m16n8k16.row.col.f32.f16.f16.f32 "
                            "{%0,%1,%2,%3}, {%4,%5,%6,%7}, {%8,%9}, {%0,%1,%2,%3};"
                            : "+f"(acc[mt][nt][0]), "+f"(acc[mt][nt][1]),
                              "+f"(acc[mt][nt][2]), "+f"(acc[mt][nt][3])
                            : "r"(a[q][mt][0]), "r"(a[q][mt][1]),
                              "r"(a[q][mt][2]), "r"(a[q][mt][3]),
                              "r"(b[q][nt][0]), "r"(b[q][nt][1]));
                    }
        }
    }

    // epilogue: fp32 acc -> fp16 store
#pragma unroll
    for (int mt = 0; mt < 4; mt++) {
#pragma unroll
        for (int nt = 0; nt < 4; nt++) {
            int gm = bm + wm * 64 + mt * 16 + (lane >> 2);
            int gn = bn + wn * 32 + nt * 8 + (lane & 3) * 2;
            *(__half2*)&C[(size_t)gm * NDIM + gn] =
                __floats2half2_rn(acc[mt][nt][0], acc[mt][nt][1]);
            *(__half2*)&C[(size_t)(gm + 8) * NDIM + gn] =
                __floats2half2_rn(acc[mt][nt][2], acc[mt][nt][3]);
        }
    }
}

// ---------------------------------------------------------------------------
// LayerNorm + LSTM cell epilogue.  One block per batch row, 256 threads.
// Reads fp16 pre-activations, computes in fp32.
// ---------------------------------------------------------------------------
__device__ __forceinline__ float sigmoidf_(float v) {
    return 1.0f / (1.0f + expf(-v));
}

__global__ void __launch_bounds__(256) ln_cell_kernel(
    const float* __restrict__ c_in,
    const float* __restrict__ b_ih,
    const float* __restrict__ gma,
    const float* __restrict__ bta,
    float* __restrict__ out)
{
    const int b   = blockIdx.x;
    const int tid = threadIdx.x;
    const int warp = tid >> 5, lane = tid & 31;

    __shared__ float s_ih[NDIM];
    __shared__ float s_hh[NDIM];
    __shared__ float stats[18];
    __shared__ float red[16];

    const uint4* pih = (const uint4*)(g_pre_ih + (size_t)b * NDIM);
    const uint4* phh = (const uint4*)(g_pre_hh + (size_t)b * NDIM);
    for (int i = tid; i < NDIM / 8; i += 256) {   // 512 uint4 per matrix row
        uint4 v = pih[i];
        const __half2* hp = (const __half2*)&v;
#pragma unroll
        for (int q = 0; q < 4; q++) {
            float2 f = __half22float2(hp[q]);
            s_ih[8 * i + 2 * q]     = f.x;
            s_ih[8 * i + 2 * q + 1] = f.y;
        }
        v = phh[i];
#pragma unroll
        for (int q = 0; q < 4; q++) {
            float2 f = __half22float2(hp[q]);
            s_hh[8 * i + 2 * q]     = f.x;
            s_hh[8 * i + 2 * q + 1] = f.y;
        }
    }
    __syncthreads();

    {
        const float* src = (warp & 1) ? s_hh : s_ih;
        const int gate = warp >> 1;
        float sum = 0.f, ss = 0.f;
        for (int j = lane; j < HDIM; j += 32) {
            float v = src[gate * HDIM + j];
            sum += v; ss += v * v;
        }
#pragma unroll
        for (int o = 16; o; o >>= 1) {
            sum += __shfl_xor_sync(0xffffffffu, sum, o);
            ss  += __shfl_xor_sync(0xffffffffu, ss,  o);
        }
        if (lane == 0) {
            float mu = sum * (1.0f / HDIM);
            stats[warp * 2]     = mu;
            stats[warp * 2 + 1] = ss * (1.0f / HDIM) - mu * mu;
        }
    }
    __syncthreads();

    float mu[8], rs[8];
#pragma unroll
    for (int t = 0; t < 8; t++) {
        mu[t] = stats[t * 2];
        rs[t] = rsqrtf(stats[t * 2 + 1] + 1e-5f);
    }

    float cvals[4], ovals[4];
    float csum = 0.f, css = 0.f;
#pragma unroll
    for (int ii = 0; ii < 4; ii++) {
        int j = tid + ii * 256;
        float gv[4];
#pragma unroll
        for (int g = 0; g < 4; g++) {
            int si = g * 2, sh = g * 2 + 1;
            float vih = s_ih[g * HDIM + j];
            float vhh = s_hh[g * HDIM + j];
            float li = gma[(2 * g) * HDIM + j] * (vih - mu[si]) * rs[si] + bta[(2 * g) * HDIM + j];
            float lh = gma[(2 * g + 1) * HDIM + j] * (vhh - mu[sh]) * rs[sh] + bta[(2 * g + 1) * HDIM + j];
            gv[g] = li + lh + b_ih[g * HDIM + j];
        }
        float ig = sigmoidf_(gv[0]);
        float fg = sigmoidf_(gv[1]);
        float ag = tanhf(gv[2]);
        float cn = fg * c_in[(size_t)b * HDIM + j] + ig * ag;
        cvals[ii] = cn;
        ovals[ii] = gv[3];
        csum += cn; css += cn * cn;
    }

#pragma unroll
    for (int o = 16; o; o >>= 1) {
        csum += __shfl_xor_sync(0xffffffffu, csum, o);
        css  += __shfl_xor_sync(0xffffffffu, css,  o);
    }
    if (lane == 0) { red[warp] = csum; red[8 + warp] = css; }
    __syncthreads();
    if (tid == 0) {
        float s = 0.f, q = 0.f;
#pragma unroll
        for (int k = 0; k < 8; k++) { s += red[k]; q += red[8 + k]; }
        float m = s * (1.0f / HDIM);
        stats[16] = m;
        stats[17] = q * (1.0f / HDIM) - m * m;
    }
    __syncthreads();

    const float cmu = stats[16];
    const float crs = rsqrtf(stats[17] + 1e-5f);
#pragma unroll
    for (int ii = 0; ii < 4; ii++) {
        int j = tid + ii * 256;
        float lnc = gma[8 * HDIM + j] * (cvals[ii] - cmu) * crs + bta[8 * HDIM + j];
        float hn = sigmoidf_(ovals[ii]) * tanhf(lnc);
        out[(size_t)b * HDIM + j] = hn;
        out[(size_t)BATCH * HDIM + (size_t)b * HDIM + j] = cvals[ii];
    }
}

// ---------------------------------------------------------------------------
// kernel_launch
// ---------------------------------------------------------------------------
extern "C" void kernel_launch(void* const* d_in, const int* in_sizes, int n_in,
                              void* d_out, int out_size)
{
    const float* x   = (const float*)d_in[0];
    const float* h   = (const float*)d_in[1];
    const float* c   = (const float*)d_in[2];
    const float* wih = (const float*)d_in[3];
    const float* whh = (const float*)d_in[4];
    const float* bih = (const float*)d_in[5];
    const float* gma = (const float*)d_in[6];
    const float* bta = (const float*)d_in[7];
    float* out = (float*)d_out;

    // 1) fp16 conversion of GEMM operands (8 elems/thread)
    dim3 cgrid(BATCH * KDIM / 8 / 256, 4);
    cvt_kernel<<<cgrid, 256>>>((const float4*)x, (const float4*)h,
                               (const float4*)wih, (const float4*)whh);

    // 2) both GEMMs in one launch (128x128 CTA, 64x32 warp, BK=64, 3-stage)
    cudaFuncSetAttribute(gemm_f16, cudaFuncAttributeMaxDynamicSharedMemorySize, SMEM_TOTAL);
    dim3 ggrid(NDIM / BN, BATCH / BM, 2);
    gemm_f16<<<ggrid, 256, SMEM_TOTAL>>>();

    // 3) layernorms + cell update (fp16 pre input)
    ln_cell_kernel<<<BATCH, 256>>>(c, bih, gma, bta, out);
}

// round 7
// speedup vs baseline: 1.0689x; 1.0689x over previous
#include <cuda_runtime.h>
#include <cuda_fp16.h>
#include <cstdint>
#include <cstddef>

// Problem sizes (fixed)
#define BATCH 4096
#define HDIM  1024
#define KDIM  1024
#define NDIM  4096

// ---------------------------------------------------------------------------
// Scratch (device globals -- allocation is forbidden)
// ---------------------------------------------------------------------------
__device__ __align__(1024) __half g_xh [BATCH * KDIM];
__device__ __align__(1024) __half g_hh [BATCH * KDIM];
__device__ __align__(1024) __half g_wih[NDIM  * KDIM];
__device__ __align__(1024) __half g_whh[NDIM  * KDIM];
__device__ __align__(16) __half g_pre_ih[(size_t)BATCH * NDIM];   // fp16 pre-activations
__device__ __align__(16) __half g_pre_hh[(size_t)BATCH * NDIM];

// ---------------------------------------------------------------------------
// fp32 -> fp16 preconversion.  Each thread: 8 floats -> 8 halves (16B store).
// ---------------------------------------------------------------------------
__global__ void __launch_bounds__(256) cvt_kernel(
    const float4* __restrict__ x, const float4* __restrict__ h,
    const float4* __restrict__ wih, const float4* __restrict__ whh)
{
    int i = blockIdx.x * blockDim.x + threadIdx.x;
    const float4* src; __half* dst;
    switch (blockIdx.y) {
        case 0:  src = x;   dst = g_xh;  break;
        case 1:  src = h;   dst = g_hh;  break;
        case 2:  src = wih; dst = g_wih; break;
        default: src = whh; dst = g_whh; break;
    }
    float4 v0 = src[2 * i];
    float4 v1 = src[2 * i + 1];
    __half2 o[4];
    o[0] = __floats2half2_rn(v0.x, v0.y);
    o[1] = __floats2half2_rn(v0.z, v0.w);
    o[2] = __floats2half2_rn(v1.x, v1.y);
    o[3] = __floats2half2_rn(v1.z, v1.w);
    *(uint4*)(dst + 8 * (size_t)i) = *(uint4*)o;
}

// ---------------------------------------------------------------------------
// fp16 GEMM: C[M,N] = A[M,K] @ W[N,K]^T, fp32 accumulate, fp16 output.
// CTA tile 128x128x32(halves), warp tile 64x32, 4-stage cp.async (single sync),
// ldmatrix batched upfront + mma.m16n8k16 dense block.   (R5 schedule)
// grid = (N/128, M/128, 2)  z: 0 = ih, 1 = hh.  block = 256 (8 warps, 2 CTA/SM)
// ---------------------------------------------------------------------------
#define BM 128
#define BN 128
#define BK 32                 // halves per k-tile (64 data bytes/row)
#define ROWB 80               // smem row stride in bytes (conflict-free LDSM)
#define STAGES 4
#define NK (KDIM / BK)        // 32
#define A_SM_BYTES (BM * ROWB)            // 10240
#define STAGE_BYTES (2 * A_SM_BYTES)      // 20480 (A then B)
#define SMEM_TOTAL (STAGES * STAGE_BYTES) // 81920  (x2 CTAs = 163840 <= 228KB)

__device__ __forceinline__ uint32_t smem_u32(const void* p) {
    uint32_t a;
    asm("{ .reg .u64 t; cvta.to.shared.u64 t, %1; cvt.u32.u64 %0, t; }" : "=r"(a) : "l"(p));
    return a;
}
__device__ __forceinline__ void cp16(uint32_t smem, const void* gmem) {
    asm volatile("cp.async.cg.shared.global [%0], [%1], 16;" :: "r"(smem), "l"(gmem));
}
#define LDSM_X4(r0, r1, r2, r3, addr) \
    asm volatile("ldmatrix.sync.aligned.m8n8.x4.shared.b16 {%0,%1,%2,%3}, [%4];" \
        : "=r"(r0), "=r"(r1), "=r"(r2), "=r"(r3) : "r"(addr))

__global__ void __launch_bounds__(256, 2) gemm_f16()
{
    extern __shared__ char smem[];
    const uint32_t sb = smem_u32(smem);
    const int tid  = threadIdx.x;
    const int lane = tid & 31;
    const int warp = tid >> 5;
    const int wm   = warp >> 2;   // 0..1 -> M 64-block
    const int wn   = warp & 3;    // 0..3 -> N 32-block

    const int z = blockIdx.z;
    const __half* __restrict__ A = z ? g_hh  : g_xh;
    const __half* __restrict__ W = z ? g_whh : g_wih;
    __half* __restrict__ C       = z ? g_pre_hh : g_pre_ih;
    const int bm = blockIdx.y * BM;
    const int bn = blockIdx.x * BN;

    float acc[4][4][4];
#pragma unroll
    for (int a = 0; a < 4; a++)
#pragma unroll
        for (int b = 0; b < 4; b++)
#pragma unroll
            for (int d = 0; d < 4; d++) acc[a][b][d] = 0.f;

    // loader: row = tid>>1 (0..127), chunk pair = (tid&1)*2 for A and B alike
    const int lrow = tid >> 1;
    const int lcp  = (tid & 1) * 2;
    const __half* gA0 = A + (size_t)(bm + lrow) * KDIM + lcp * 8;
    const __half* gW0 = W + (size_t)(bn + lrow) * KDIM + lcp * 8;
    const uint32_t sA0 = sb + lrow * ROWB + lcp * 16;
    const uint32_t sB0 = sA0 + A_SM_BYTES;

    auto issue = [&](int kt) {
        const int buf = kt & (STAGES - 1);
        const size_t ko = (size_t)kt * BK;
        const uint32_t so = buf * STAGE_BYTES;
        cp16(sA0 + so,      gA0 + ko);
        cp16(sA0 + so + 16, gA0 + ko + 8);
        cp16(sB0 + so,      gW0 + ko);
        cp16(sB0 + so + 16, gW0 + ko + 8);
        asm volatile("cp.async.commit_group;");
    };

    issue(0); issue(1); issue(2);

    // fragment base addresses (per thread)
    const int l15 = lane & 15, lhi = lane >> 4;
    const uint32_t aBase = sb + (wm * 64 + l15) * ROWB + lhi * 16;
    const uint32_t bBase = sb + A_SM_BYTES + (wn * 32 + l15) * ROWB + lhi * 16;

    for (int kt = 0; kt < NK; kt++) {
        const int buf = kt & (STAGES - 1);
        if (kt < NK - 2) {
            asm volatile("cp.async.wait_group 2;");
        } else if (kt == NK - 2) {
            asm volatile("cp.async.wait_group 1;");
        } else {
            asm volatile("cp.async.wait_group 0;");
        }
        __syncthreads();
        if (kt + 3 < NK) issue(kt + 3);   // writes buf (kt-1)&3: reads done pre-sync

        const uint32_t so = buf * STAGE_BYTES;

        // ---- batch ALL fragment loads for both k16 slices ----
        uint32_t a[2][4][4];   // [ks][mt][reg]
        uint32_t b[2][4][2];   // [ks][nt][reg]
#pragma unroll
        for (int ks = 0; ks < 2; ks++) {
#pragma unroll
            for (int mt = 0; mt < 4; mt++)
                LDSM_X4(a[ks][mt][0], a[ks][mt][1], a[ks][mt][2], a[ks][mt][3],
                        aBase + so + mt * (16 * ROWB) + ks * 32);
            LDSM_X4(b[ks][0][0], b[ks][1][0], b[ks][0][1], b[ks][1][1],
                    bBase + so + ks * 32);
            LDSM_X4(b[ks][2][0], b[ks][3][0], b[ks][2][1], b[ks][3][1],
                    bBase + so + 16 * ROWB + ks * 32);
        }

        // ---- dense MMA block (32 HMMA) ----
#pragma unroll
        for (int ks = 0; ks < 2; ks++)
#pragma unroll
            for (int mt = 0; mt < 4; mt++)
#pragma unroll
                for (int nt = 0; nt < 4; nt++) {
                    asm volatile(
                        "mma.sync.aligned.m16n8k16.row.col.f32.f16.f16.f32 "
                        "{%0,%1,%2,%3}, {%4,%5,%6,%7}, {%8,%9}, {%0,%1,%2,%3};"
                        : "+f"(acc[mt][nt][0]), "+f"(acc[mt][nt][1]),
                          "+f"(acc[mt][nt][2]), "+f"(acc[mt][nt][3])
                        : "r"(a[ks][mt][0]), "r"(a[ks][mt][1]),
                          "r"(a[ks][mt][2]), "r"(a[ks][mt][3]),
                          "r"(b[ks][nt][0]), "r"(b[ks][nt][1]));
                }
    }

    // epilogue: fp32 acc -> fp16 store
#pragma unroll
    for (int mt = 0; mt < 4; mt++) {
#pragma unroll
        for (int nt = 0; nt < 4; nt++) {
            int gm = bm + wm * 64 + mt * 16 + (lane >> 2);
            int gn = bn + wn * 32 + nt * 8 + (lane & 3) * 2;
            *(__half2*)&C[(size_t)gm * NDIM + gn] =
                __floats2half2_rn(acc[mt][nt][0], acc[mt][nt][1]);
            *(__half2*)&C[(size_t)(gm + 8) * NDIM + gn] =
                __floats2half2_rn(acc[mt][nt][2], acc[mt][nt][3]);
        }
    }
}

// ---------------------------------------------------------------------------
// LayerNorm + LSTM cell epilogue.  One block per batch row, 256 threads.
// Reads fp16 pre-activations, computes in fp32.
// ---------------------------------------------------------------------------
__device__ __forceinline__ float sigmoidf_(float v) {
    return 1.0f / (1.0f + expf(-v));
}

__global__ void __launch_bounds__(256) ln_cell_kernel(
    const float* __restrict__ c_in,
    const float* __restrict__ b_ih,
    const float* __restrict__ gma,
    const float* __restrict__ bta,
    float* __restrict__ out)
{
    const int b   = blockIdx.x;
    const int tid = threadIdx.x;
    const int warp = tid >> 5, lane = tid & 31;

    __shared__ float s_ih[NDIM];
    __shared__ float s_hh[NDIM];
    __shared__ float stats[18];
    __shared__ float red[16];

    const uint4* pih = (const uint4*)(g_pre_ih + (size_t)b * NDIM);
    const uint4* phh = (const uint4*)(g_pre_hh + (size_t)b * NDIM);
    for (int i = tid; i < NDIM / 8; i += 256) {   // 512 uint4 per matrix row
        uint4 v = pih[i];
        const __half2* hp = (const __half2*)&v;
#pragma unroll
        for (int q = 0; q < 4; q++) {
            float2 f = __half22float2(hp[q]);
            s_ih[8 * i + 2 * q]     = f.x;
            s_ih[8 * i + 2 * q + 1] = f.y;
        }
        v = phh[i];
#pragma unroll
        for (int q = 0; q < 4; q++) {
            float2 f = __half22float2(hp[q]);
            s_hh[8 * i + 2 * q]     = f.x;
            s_hh[8 * i + 2 * q + 1] = f.y;
        }
    }
    __syncthreads();

    {
        const float* src = (warp & 1) ? s_hh : s_ih;
        const int gate = warp >> 1;
        float sum = 0.f, ss = 0.f;
        for (int j = lane; j < HDIM; j += 32) {
            float v = src[gate * HDIM + j];
            sum += v; ss += v * v;
        }
#pragma unroll
        for (int o = 16; o; o >>= 1) {
            sum += __shfl_xor_sync(0xffffffffu, sum, o);
            ss  += __shfl_xor_sync(0xffffffffu, ss,  o);
        }
        if (lane == 0) {
            float mu = sum * (1.0f / HDIM);
            stats[warp * 2]     = mu;
            stats[warp * 2 + 1] = ss * (1.0f / HDIM) - mu * mu;
        }
    }
    __syncthreads();

    float mu[8], rs[8];
#pragma unroll
    for (int t = 0; t < 8; t++) {
        mu[t] = stats[t * 2];
        rs[t] = rsqrtf(stats[t * 2 + 1] + 1e-5f);
    }

    float cvals[4], ovals[4];
    float csum = 0.f, css = 0.f;
#pragma unroll
    for (int ii = 0; ii < 4; ii++) {
        int j = tid + ii * 256;
        float gv[4];
#pragma unroll
        for (int g = 0; g < 4; g++) {
            int si = g * 2, sh = g * 2 + 1;
            float vih = s_ih[g * HDIM + j];
            float vhh = s_hh[g * HDIM + j];
            float li = gma[(2 * g) * HDIM + j] * (vih - mu[si]) * rs[si] + bta[(2 * g) * HDIM + j];
            float lh = gma[(2 * g + 1) * HDIM + j] * (vhh - mu[sh]) * rs[sh] + bta[(2 * g + 1) * HDIM + j];
            gv[g] = li + lh + b_ih[g * HDIM + j];
        }
        float ig = sigmoidf_(gv[0]);
        float fg = sigmoidf_(gv[1]);
        float ag = tanhf(gv[2]);
        float cn = fg * c_in[(size_t)b * HDIM + j] + ig * ag;
        cvals[ii] = cn;
        ovals[ii] = gv[3];
        csum += cn; css += cn * cn;
    }

#pragma unroll
    for (int o = 16; o; o >>= 1) {
        csum += __shfl_xor_sync(0xffffffffu, csum, o);
        css  += __shfl_xor_sync(0xffffffffu, css,  o);
    }
    if (lane == 0) { red[warp] = csum; red[8 + warp] = css; }
    __syncthreads();
    if (tid == 0) {
        float s = 0.f, q = 0.f;
#pragma unroll
        for (int k = 0; k < 8; k++) { s += red[k]; q += red[8 + k]; }
        float m = s * (1.0f / HDIM);
        stats[16] = m;
        stats[17] = q * (1.0f / HDIM) - m * m;
    }
    __syncthreads();

    const float cmu = stats[16];
    const float crs = rsqrtf(stats[17] + 1e-5f);
#pragma unroll
    for (int ii = 0; ii < 4; ii++) {
        int j = tid + ii * 256;
        float lnc = gma[8 * HDIM + j] * (cvals[ii] - cmu) * crs + bta[8 * HDIM + j];
        float hn = sigmoidf_(ovals[ii]) * tanhf(lnc);
        out[(size_t)b * HDIM + j] = hn;
        out[(size_t)BATCH * HDIM + (size_t)b * HDIM + j] = cvals[ii];
    }
}

// ---------------------------------------------------------------------------
// kernel_launch
// ---------------------------------------------------------------------------
extern "C" void kernel_launch(void* const* d_in, const int* in_sizes, int n_in,
                              void* d_out, int out_size)
{
    const float* x   = (const float*)d_in[0];
    const float* h   = (const float*)d_in[1];
    const float* c   = (const float*)d_in[2];
    const float* wih = (const float*)d_in[3];
    const float* whh = (const float*)d_in[4];
    const float* bih = (const float*)d_in[5];
    const float* gma = (const float*)d_in[6];
    const float* bta = (const float*)d_in[7];
    float* out = (float*)d_out;

    // 1) fp16 conversion of GEMM operands (8 elems/thread)
    dim3 cgrid(BATCH * KDIM / 8 / 256, 4);
    cvt_kernel<<<cgrid, 256>>>((const float4*)x, (const float4*)h,
                               (const float4*)wih, (const float4*)whh);

    // 2) both GEMMs in one launch (R5 schedule: BK=32, 4-stage, single sync)
    cudaFuncSetAttribute(gemm_f16, cudaFuncAttributeMaxDynamicSharedMemorySize, SMEM_TOTAL);
    dim3 ggrid(NDIM / BN, BATCH / BM, 2);
    gemm_f16<<<ggrid, 256, SMEM_TOTAL>>>();

    // 3) layernorms + cell update (fp16 pre input)
    ln_cell_kernel<<<BATCH, 256>>>(c, bih, gma, bta, out);
}